// round 1
// baseline (speedup 1.0000x reference)
#include <cuda_runtime.h>

#define B_  4
#define S_  2048
#define D_  1024
#define H_  16
#define DK  64
#define MTOK (B_*S_)   // 8192

// Scratch in (b, h, s, d) layout: ((b*H + h)*S + s)*DK + d
__device__ float g_Q[(size_t)B_*H_*S_*DK];
__device__ float g_K[(size_t)B_*H_*S_*DK];
__device__ float g_V[(size_t)B_*H_*S_*DK];

// ---------------------------------------------------------------------------
// Fused dual-linear QKV projection:
//   C[t, c] = sum_k Xs[t,k]*Ws[c,k] + sum_k Xt[t,k]*Wt[c,k] + bs[c] + bt[c]
// M = 8192 tokens, N = 3072 (Q|K|V each 1024), K = 1024 per phase (2 phases).
// Classic SGEMM: BM=BN=128, BK=8, 256 threads, 8x8 micro-tile.
// ---------------------------------------------------------------------------
__global__ __launch_bounds__(256) void qkv_gemm(
    const float* __restrict__ Xs, const float* __restrict__ Xt,
    const float* __restrict__ Wqs, const float* __restrict__ bqs,
    const float* __restrict__ Wqt, const float* __restrict__ bqt,
    const float* __restrict__ Wks, const float* __restrict__ bks,
    const float* __restrict__ Wkt, const float* __restrict__ bkt,
    const float* __restrict__ Wvs, const float* __restrict__ bvs,
    const float* __restrict__ Wvt, const float* __restrict__ bvt)
{
    const int bm = blockIdx.x;           // 64 tiles of 128 tokens
    const int bn = blockIdx.y;           // 24 tiles of 128 channels
    const int mi = bn >> 3;              // 0=Q, 1=K, 2=V
    const int n0 = (bn & 7) * 128;       // channel offset within matrix
    const int m0 = bm * 128;

    const float* Ws = (mi == 0) ? Wqs : (mi == 1) ? Wks : Wvs;
    const float* Wt = (mi == 0) ? Wqt : (mi == 1) ? Wkt : Wvt;
    const float* bs = (mi == 0) ? bqs : (mi == 1) ? bks : bvs;
    const float* bt = (mi == 0) ? bqt : (mi == 1) ? bkt : bvt;
    float* Out      = (mi == 0) ? g_Q : (mi == 1) ? g_K : g_V;

    __shared__ float As[8][128];
    __shared__ float Bs[8][128];

    const int tid = threadIdx.x;
    const int tx  = tid & 15;
    const int ty  = tid >> 4;

    float acc[8][8];
    #pragma unroll
    for (int i = 0; i < 8; i++)
        #pragma unroll
        for (int j = 0; j < 8; j++) acc[i][j] = 0.f;

    const int lr = tid >> 1;             // 0..127 loader row
    const int lk = (tid & 1) * 4;        // 0 or 4

    #pragma unroll 1
    for (int phase = 0; phase < 2; phase++) {
        const float* X = phase ? Xt : Xs;
        const float* W = phase ? Wt : Ws;
        #pragma unroll 1
        for (int k0 = 0; k0 < D_; k0 += 8) {
            float4 a = *(const float4*)&X[(size_t)(m0 + lr) * D_ + k0 + lk];
            float4 b = *(const float4*)&W[(size_t)(n0 + lr) * D_ + k0 + lk];
            __syncthreads();   // previous-iter compute done before overwrite
            As[lk + 0][lr] = a.x; As[lk + 1][lr] = a.y;
            As[lk + 2][lr] = a.z; As[lk + 3][lr] = a.w;
            Bs[lk + 0][lr] = b.x; Bs[lk + 1][lr] = b.y;
            Bs[lk + 2][lr] = b.z; Bs[lk + 3][lr] = b.w;
            __syncthreads();
            #pragma unroll
            for (int kk = 0; kk < 8; kk++) {
                float4 a0 = *(const float4*)&As[kk][ty * 8];
                float4 a1 = *(const float4*)&As[kk][ty * 8 + 4];
                float4 b0 = *(const float4*)&Bs[kk][tx * 8];
                float4 b1 = *(const float4*)&Bs[kk][tx * 8 + 4];
                float ra[8] = {a0.x, a0.y, a0.z, a0.w, a1.x, a1.y, a1.z, a1.w};
                float rb[8] = {b0.x, b0.y, b0.z, b0.w, b1.x, b1.y, b1.z, b1.w};
                #pragma unroll
                for (int i = 0; i < 8; i++)
                    #pragma unroll
                    for (int j = 0; j < 8; j++)
                        acc[i][j] += ra[i] * rb[j];
            }
        }
    }

    // epilogue: add both biases, scatter to (b,h,s,d)
    #pragma unroll
    for (int i = 0; i < 8; i++) {
        int t  = m0 + ty * 8 + i;
        int bb = t >> 11;          // /2048
        int ss = t & 2047;
        #pragma unroll
        for (int j = 0; j < 8; j++) {
            int c = n0 + tx * 8 + j;
            int h = c >> 6, d = c & 63;
            float v = acc[i][j] + bs[c] + bt[c];
            Out[(((size_t)(bb * H_ + h)) * S_ + ss) * DK + d] = v;
        }
    }
}

// ---------------------------------------------------------------------------
// Flash attention, fp32. One block = 64 query rows of one (b,h).
// 256 threads as 16x16; each thread owns 4q x 4k scores and 4q x 4d output.
// Online softmax with 16-lane shuffle reductions across tx.
// Smem: Qt/Kt transposed [d][row] for conflict-free LDS.128 in QK^T;
//       V natural [k][d]; P stored [q][k] overlaid on Kt buffer.
// ---------------------------------------------------------------------------
#define BQ 64
#define BK 64

__global__ __launch_bounds__(256) void attn_kernel(
    const float* __restrict__ bias_p, float* __restrict__ out)
{
    const int qt = blockIdx.x;           // 0..31 query tile
    const int bh = blockIdx.y;           // 0..63 (b*H + h)
    const float* Q = g_Q + (size_t)bh * S_ * DK;
    const float* K = g_K + (size_t)bh * S_ * DK;
    const float* V = g_V + (size_t)bh * S_ * DK;
    const int q0 = qt * BQ;
    const float bias = bias_p[0];

    __shared__ float Qt_s[64][64];       // [d][q], pre-scaled by 1/8
    __shared__ float KtP[64][64];        // [d][k] for K^T, then reused as P[q][k]
    __shared__ float Vs[64][64];         // [k][d]

    const int tid = threadIdx.x;
    const int tx  = tid & 15;
    const int ty  = tid >> 4;

    // ---- load Q tile, transposed + scaled by 1/sqrt(dk) = 0.125 ----
    {
        int r  = tid >> 2;               // query row 0..63
        int d0 = (tid & 3) * 16;
        #pragma unroll
        for (int u = 0; u < 4; u++) {
            float4 v = *(const float4*)&Q[(size_t)(q0 + r) * DK + d0 + u * 4];
            Qt_s[d0 + u * 4 + 0][r] = v.x * 0.125f;
            Qt_s[d0 + u * 4 + 1][r] = v.y * 0.125f;
            Qt_s[d0 + u * 4 + 2][r] = v.z * 0.125f;
            Qt_s[d0 + u * 4 + 3][r] = v.w * 0.125f;
        }
    }

    float m_run[4], l_run[4], o[4][4];
    #pragma unroll
    for (int i = 0; i < 4; i++) {
        m_run[i] = -1e30f; l_run[i] = 0.f;
        #pragma unroll
        for (int j = 0; j < 4; j++) o[i][j] = 0.f;
    }

    #pragma unroll 1
    for (int k0 = 0; k0 < S_; k0 += BK) {
        // ---- load K (transposed) and V (natural) for this chunk ----
        int r  = tid >> 2;
        int d0 = (tid & 3) * 16;
        float4 kreg[4], vreg[4];
        #pragma unroll
        for (int u = 0; u < 4; u++) {
            kreg[u] = *(const float4*)&K[(size_t)(k0 + r) * DK + d0 + u * 4];
            vreg[u] = *(const float4*)&V[(size_t)(k0 + r) * DK + d0 + u * 4];
        }
        __syncthreads();  // everyone done with previous P / V
        #pragma unroll
        for (int u = 0; u < 4; u++) {
            KtP[d0 + u * 4 + 0][r] = kreg[u].x;
            KtP[d0 + u * 4 + 1][r] = kreg[u].y;
            KtP[d0 + u * 4 + 2][r] = kreg[u].z;
            KtP[d0 + u * 4 + 3][r] = kreg[u].w;
            *(float4*)&Vs[r][d0 + u * 4] = vreg[u];
        }
        __syncthreads();

        // ---- scores s[i][j]: q rows ty*4+i, k cols tx*4+j ----
        float s[4][4];
        #pragma unroll
        for (int i = 0; i < 4; i++)
            #pragma unroll
            for (int j = 0; j < 4; j++) s[i][j] = 0.f;
        #pragma unroll
        for (int dd = 0; dd < 64; dd++) {
            float4 qv = *(const float4*)&Qt_s[dd][ty * 4];
            float4 kv = *(const float4*)&KtP[dd][tx * 4];
            float rq[4] = {qv.x, qv.y, qv.z, qv.w};
            float rk[4] = {kv.x, kv.y, kv.z, kv.w};
            #pragma unroll
            for (int i = 0; i < 4; i++)
                #pragma unroll
                for (int j = 0; j < 4; j++)
                    s[i][j] += rq[i] * rk[j];
        }

        // ---- online softmax (rows reduced across tx via shfl) ----
        float p[4][4];
        #pragma unroll
        for (int i = 0; i < 4; i++) {
            float mx = s[i][0];
            #pragma unroll
            for (int j = 1; j < 4; j++) mx = fmaxf(mx, s[i][j]);
            #pragma unroll
            for (int w = 1; w < 16; w <<= 1)
                mx = fmaxf(mx, __shfl_xor_sync(0xffffffffu, mx, w, 32));
            float mnew = fmaxf(m_run[i], mx + bias);
            float scale = __expf(m_run[i] - mnew);
            m_run[i] = mnew;
            float rs = 0.f;
            #pragma unroll
            for (int j = 0; j < 4; j++) {
                p[i][j] = __expf(s[i][j] + bias - mnew);
                rs += p[i][j];
            }
            #pragma unroll
            for (int w = 1; w < 16; w <<= 1)
                rs += __shfl_xor_sync(0xffffffffu, rs, w, 32);
            l_run[i] = l_run[i] * scale + rs;
            #pragma unroll
            for (int j = 0; j < 4; j++) o[i][j] *= scale;
        }

        // ---- write P into KtP buffer as P[q][k] (float4 stores) ----
        __syncthreads();  // all threads done reading Kt
        #pragma unroll
        for (int i = 0; i < 4; i++)
            *(float4*)&KtP[ty * 4 + i][tx * 4] =
                make_float4(p[i][0], p[i][1], p[i][2], p[i][3]);
        __syncthreads();

        // ---- O += P @ V: o rows ty*4+i, d cols tx*4+j ----
        #pragma unroll
        for (int kk = 0; kk < 64; kk++) {
            float rp[4];
            #pragma unroll
            for (int i = 0; i < 4; i++) rp[i] = KtP[ty * 4 + i][kk]; // broadcast
            float4 vv = *(const float4*)&Vs[kk][tx * 4];
            float rv[4] = {vv.x, vv.y, vv.z, vv.w};
            #pragma unroll
            for (int i = 0; i < 4; i++)
                #pragma unroll
                for (int j = 0; j < 4; j++)
                    o[i][j] += rp[i] * rv[j];
        }
    }

    // ---- normalize and write out in (b, s, h*64+d) ----
    const int bb = bh >> 4;
    const int hh = bh & 15;
    #pragma unroll
    for (int i = 0; i < 4; i++) {
        int qq = q0 + ty * 4 + i;
        float inv = 1.f / l_run[i];
        #pragma unroll
        for (int j = 0; j < 4; j++) {
            out[((size_t)(bb * S_ + qq)) * D_ + hh * DK + tx * 4 + j] =
                o[i][j] * inv;
        }
    }
}

// ---------------------------------------------------------------------------
extern "C" void kernel_launch(void* const* d_in, const int* in_sizes, int n_in,
                              void* d_out, int out_size)
{
    const float* Xs  = (const float*)d_in[0];
    const float* Xt  = (const float*)d_in[1];
    const float* Wqs = (const float*)d_in[2];
    const float* bqs = (const float*)d_in[3];
    const float* Wqt = (const float*)d_in[4];
    const float* bqt = (const float*)d_in[5];
    const float* Wks = (const float*)d_in[6];
    const float* bks = (const float*)d_in[7];
    const float* Wkt = (const float*)d_in[8];
    const float* bkt = (const float*)d_in[9];
    const float* Wvs = (const float*)d_in[10];
    const float* bvs = (const float*)d_in[11];
    const float* Wvt = (const float*)d_in[12];
    const float* bvt = (const float*)d_in[13];
    const float* attn_bias = (const float*)d_in[14];
    float* out = (float*)d_out;

    dim3 gGrid(MTOK / 128, 3 * D_ / 128);   // (64, 24)
    qkv_gemm<<<gGrid, 256>>>(Xs, Xt, Wqs, bqs, Wqt, bqt,
                             Wks, bks, Wkt, bkt, Wvs, bvs, Wvt, bvt);

    dim3 aGrid(S_ / BQ, B_ * H_);           // (32, 64)
    attn_kernel<<<aGrid, 256>>>(attn_bias, out);
}

// round 3
// speedup vs baseline: 2.8845x; 2.8845x over previous
#include <cuda_runtime.h>
#include <cstdint>

#define B_  4
#define S_  2048
#define D_  1024
#define H_  16
#define DK  64

// Scratch Q/K/V in (b, h, s, d) layout
__device__ float g_Q[(size_t)B_*H_*S_*DK];
__device__ float g_K[(size_t)B_*H_*S_*DK];
__device__ float g_V[(size_t)B_*H_*S_*DK];

// ---------------------------------------------------------------------------
// Portable PTX helpers (sm_80-level: ldmatrix + tf32 mma.sync)
// ---------------------------------------------------------------------------
__device__ __forceinline__ uint32_t smem_u32(const void* p) {
    uint32_t a;
    asm("{ .reg .u64 t; cvta.to.shared.u64 t, %1; cvt.u32.u64 %0, t; }"
        : "=r"(a) : "l"(p));
    return a;
}
__device__ __forceinline__ uint32_t tf32r(float f) {
    uint32_t u;
    asm("cvt.rna.tf32.f32 %0, %1;" : "=r"(u) : "f"(f));
    return u;
}
__device__ __forceinline__ void ldsm4(uint32_t r[4], uint32_t a) {
    asm volatile("ldmatrix.sync.aligned.m8n8.x4.shared.b16 {%0,%1,%2,%3}, [%4];"
        : "=r"(r[0]), "=r"(r[1]), "=r"(r[2]), "=r"(r[3]) : "r"(a));
}
__device__ __forceinline__ void mma8(float* c, const uint32_t* a,
                                     uint32_t b0, uint32_t b1) {
    asm volatile("mma.sync.aligned.m16n8k8.row.col.f32.tf32.tf32.f32 "
        "{%0,%1,%2,%3}, {%4,%5,%6,%7}, {%8,%9}, {%0,%1,%2,%3};"
        : "+f"(c[0]), "+f"(c[1]), "+f"(c[2]), "+f"(c[3])
        : "r"(a[0]), "r"(a[1]), "r"(a[2]), "r"(a[3]), "r"(b0), "r"(b1));
}

// Swizzles (quad = 16B unit within a row)
// 16-float rows (64B): q in 0..3
#define SWZ16(row, q) (((q) ^ (((row) >> 1) & 3)) & 3)
// 64-float rows (256B): q in 0..15
#define SWZ64(row, q) (((q) & 8) | ((((q) ^ ((row) & 7) ^ (((row) >> 3) & 7))) & 7))

// ---------------------------------------------------------------------------
// QKV dual-linear GEMM: C[t,c] = sum_k Xs[t,k]Ws[c,k] + Xt[t,k]Wt[c,k] + b
// M=8192, N=3072 (Q|K|V), K=2x1024. Block 128x128, BK=16, 8 warps (64x32 each)
// ---------------------------------------------------------------------------
__global__ __launch_bounds__(256) void qkv_gemm_mma(
    const float* __restrict__ Xs, const float* __restrict__ Xt,
    const float* __restrict__ Wqs, const float* __restrict__ bqs,
    const float* __restrict__ Wqt, const float* __restrict__ bqt,
    const float* __restrict__ Wks, const float* __restrict__ bks,
    const float* __restrict__ Wkt, const float* __restrict__ bkt,
    const float* __restrict__ Wvs, const float* __restrict__ bvs,
    const float* __restrict__ Wvt, const float* __restrict__ bvt)
{
    __shared__ uint32_t As[2][128 * 16];
    __shared__ uint32_t Bs[2][128 * 16];

    const int tid = threadIdx.x;
    const int lane = tid & 31;
    const int wid = tid >> 5;
    const int wr = wid >> 2;          // 0..1 (64-row blocks)
    const int wc = wid & 3;           // 0..3 (32-col blocks)

    const int bm = blockIdx.x;
    const int bn = blockIdx.y;
    const int mi = bn >> 3;           // 0=Q, 1=K, 2=V
    const int n0 = (bn & 7) * 128;
    const int m0 = bm * 128;

    const float* Ws = (mi == 0) ? Wqs : (mi == 1) ? Wks : Wvs;
    const float* Wt = (mi == 0) ? Wqt : (mi == 1) ? Wkt : Wvt;
    const float* bsp = (mi == 0) ? bqs : (mi == 1) ? bks : bvs;
    const float* btp = (mi == 0) ? bqt : (mi == 1) ? bkt : bvt;
    float* Out = (mi == 0) ? g_Q : (mi == 1) ? g_K : g_V;

    float acc[4][4][4];
    #pragma unroll
    for (int mt = 0; mt < 4; mt++)
        #pragma unroll
        for (int nt = 0; nt < 4; nt++)
            #pragma unroll
            for (int r = 0; r < 4; r++) acc[mt][nt][r] = 0.f;

    // loader: thread covers row lrow, 8 consecutive k (2 quads) at half lh
    const int lrow = tid >> 1;
    const int lh = tid & 1;
    const float* gXrow[2] = { Xs + (size_t)(m0 + lrow) * D_ + lh * 8,
                              Xt + (size_t)(m0 + lrow) * D_ + lh * 8 };
    const float* gWrow[2] = { Ws + (size_t)(n0 + lrow) * D_ + lh * 8,
                              Wt + (size_t)(n0 + lrow) * D_ + lh * 8 };
    const int sidx0 = lrow * 16 + SWZ16(lrow, lh * 2) * 4;
    const int sidx1 = lrow * 16 + SWZ16(lrow, lh * 2 + 1) * 4;

    float4 rA0, rA1, rB0, rB1;
    rA0 = *(const float4*)(gXrow[0]);
    rA1 = *(const float4*)(gXrow[0] + 4);
    rB0 = *(const float4*)(gWrow[0]);
    rB1 = *(const float4*)(gWrow[0] + 4);

    const int brow = wc * 32 + (lane & 7);
    const uint32_t bq = lane >> 3;
    const int arow = wr * 64 + (lane & 15);

    #pragma unroll 1
    for (int it = 0; it < 128; it++) {
        const int buf = it & 1;
        // STS staged chunk (round to tf32 here)
        {
            uint4 a0 = make_uint4(tf32r(rA0.x), tf32r(rA0.y), tf32r(rA0.z), tf32r(rA0.w));
            uint4 a1 = make_uint4(tf32r(rA1.x), tf32r(rA1.y), tf32r(rA1.z), tf32r(rA1.w));
            uint4 b0 = make_uint4(tf32r(rB0.x), tf32r(rB0.y), tf32r(rB0.z), tf32r(rB0.w));
            uint4 b1 = make_uint4(tf32r(rB1.x), tf32r(rB1.y), tf32r(rB1.z), tf32r(rB1.w));
            *(uint4*)&As[buf][sidx0] = a0;
            *(uint4*)&As[buf][sidx1] = a1;
            *(uint4*)&Bs[buf][sidx0] = b0;
            *(uint4*)&Bs[buf][sidx1] = b1;
        }
        // prefetch next chunk
        if (it < 127) {
            const int nit = it + 1;
            const int ph = nit >> 6;
            const int k0 = (nit & 63) * 16;
            rA0 = *(const float4*)(gXrow[ph] + k0);
            rA1 = *(const float4*)(gXrow[ph] + k0 + 4);
            rB0 = *(const float4*)(gWrow[ph] + k0);
            rB1 = *(const float4*)(gWrow[ph] + k0 + 4);
        }
        __syncthreads();

        const uint32_t aBase = smem_u32(&As[buf][0]);
        const uint32_t bBase = smem_u32(&Bs[buf][0]);

        uint32_t bfr[4][4];
        const uint32_t baddr = bBase + brow * 64 + SWZ16(brow, bq) * 16;
        #pragma unroll
        for (int nt = 0; nt < 4; nt++)
            ldsm4(bfr[nt], baddr + nt * 512);

        #pragma unroll
        for (int ks = 0; ks < 2; ks++) {
            const uint32_t aq = ks * 2 + (lane >> 4);
            const uint32_t aaddr = aBase + arow * 64 + SWZ16(arow, aq) * 16;
            uint32_t af[4][4];
            #pragma unroll
            for (int mt = 0; mt < 4; mt++)
                ldsm4(af[mt], aaddr + mt * 1024);
            #pragma unroll
            for (int mt = 0; mt < 4; mt++)
                #pragma unroll
                for (int nt = 0; nt < 4; nt++)
                    mma8(acc[mt][nt], af[mt], bfr[nt][ks * 2], bfr[nt][ks * 2 + 1]);
        }
        __syncthreads();
    }

    // Epilogue: add both biases, scatter to (b,h,s,d)
    const int r4 = lane >> 2;
    const int q2 = (lane & 3) * 2;
    #pragma unroll
    for (int mt = 0; mt < 4; mt++) {
        const int t = m0 + wr * 64 + mt * 16 + r4;
        #pragma unroll
        for (int nt = 0; nt < 4; nt++) {
            const int c0 = n0 + wc * 32 + nt * 8 + q2;
            const float bx = bsp[c0] + btp[c0];
            const float by = bsp[c0 + 1] + btp[c0 + 1];
            const int h = c0 >> 6, d = c0 & 63;
            #pragma unroll
            for (int half = 0; half < 2; half++) {
                const int tt = t + half * 8;
                const int bb = tt >> 11;
                const int ss = tt & 2047;
                float2 v;
                v.x = acc[mt][nt][half * 2 + 0] + bx;
                v.y = acc[mt][nt][half * 2 + 1] + by;
                *(float2*)&Out[(((size_t)(bb * H_ + h)) * S_ + ss) * DK + d] = v;
            }
        }
    }
}

// ---------------------------------------------------------------------------
// Flash attention (tf32 mma.sync). BQ=128 (8 warps x 16 rows), BK=64, dk=64.
// ---------------------------------------------------------------------------
__global__ __launch_bounds__(256) void attn_mma(
    const float* __restrict__ bias_p, float* __restrict__ out)
{
    extern __shared__ uint32_t smem[];
    uint32_t* Qs = smem;                // 128*64 = 8192 elems
    uint32_t* Ks = smem + 8192;         // 64*64  = 4096
    uint32_t* Vt = smem + 12288;        // 64*64  = 4096 (d-major, k cols)
    uint32_t* Ps = smem + 16384;        // 128*64 = 8192

    const int tid = threadIdx.x;
    const int lane = tid & 31;
    const int wid = tid >> 5;

    const int qt = blockIdx.x;          // 0..15
    const int bh = blockIdx.y;          // 0..63
    const int q0 = qt * 128;
    const float* Q = g_Q + (size_t)bh * S_ * DK;
    const float* K = g_K + (size_t)bh * S_ * DK;
    const float* V = g_V + (size_t)bh * S_ * DK;
    const float cb = bias_p[0];
    const float SC = 0.125f;            // 1/sqrt(64)

    // ---- stage Q (rounded to tf32) ----
    {
        const int row = tid >> 1;
        const int h = tid & 1;
        const float* gq = Q + (size_t)(q0 + row) * DK + h * 32;
        #pragma unroll
        for (int u = 0; u < 8; u++) {
            float4 v = *(const float4*)(gq + u * 4);
            const int q = h * 8 + u;
            const int idx = row * 64 + SWZ64(row, q) * 4;
            *(uint4*)&Qs[idx] =
                make_uint4(tf32r(v.x), tf32r(v.y), tf32r(v.z), tf32r(v.w));
        }
    }

    float o[8][4];
    #pragma unroll
    for (int nt = 0; nt < 8; nt++)
        #pragma unroll
        for (int r = 0; r < 4; r++) o[nt][r] = 0.f;
    float m0r = -1e30f, m1r = -1e30f, l0 = 0.f, l1 = 0.f;

    const uint32_t smQ = smem_u32(Qs);
    const uint32_t smK = smem_u32(Ks);
    const uint32_t smV = smem_u32(Vt);
    const uint32_t smP = smem_u32(Ps);

    const int arow = wid * 16 + (lane & 15);
    const int aqh = lane >> 4;          // 0/1
    const int b8 = lane & 7;
    const int bqh = lane >> 3;          // 0..3
    const int r4 = lane >> 2;
    const int q2 = (lane & 3) * 2;

    #pragma unroll 1
    for (int kc = 0; kc < 32; kc++) {
        // ---- load K chunk + V chunk (V transposed), tf32-rounded ----
        {
            const int row = tid >> 2;       // key index 0..63
            const int qg = tid & 3;         // 16-float group
            const float* gk = K + (size_t)(kc * 64 + row) * DK + qg * 16;
            const float* gv = V + (size_t)(kc * 64 + row) * DK + qg * 16;
            float4 kv[4], vv[4];
            #pragma unroll
            for (int u = 0; u < 4; u++) {
                kv[u] = *(const float4*)(gk + u * 4);
                vv[u] = *(const float4*)(gv + u * 4);
            }
            __syncthreads();  // previous chunk's compute done before overwrite
            #pragma unroll
            for (int u = 0; u < 4; u++) {
                const int q = qg * 4 + u;
                const int idx = row * 64 + SWZ64(row, q) * 4;
                *(uint4*)&Ks[idx] =
                    make_uint4(tf32r(kv[u].x), tf32r(kv[u].y), tf32r(kv[u].z), tf32r(kv[u].w));
                // V transpose: element (k=row, d=qg*16+u*4+i) -> Vt[d][k]
                #pragma unroll
                for (int i = 0; i < 4; i++) {
                    const int d = qg * 16 + u * 4 + i;
                    const float val = (i == 0) ? vv[u].x : (i == 1) ? vv[u].y
                                    : (i == 2) ? vv[u].z : vv[u].w;
                    Vt[d * 64 + SWZ64(d, row >> 2) * 4 + (row & 3)] = tf32r(val);
                }
            }
            __syncthreads();
        }

        // ---- S = Q K^T (per-warp 16x64) ----
        float s[8][4];
        #pragma unroll
        for (int nt = 0; nt < 8; nt++)
            #pragma unroll
            for (int r = 0; r < 4; r++) s[nt][r] = 0.f;

        #pragma unroll
        for (int p = 0; p < 4; p++) {
            uint32_t af0[4], af1[4];
            {
                const uint32_t q = 4 * p + aqh;
                ldsm4(af0, smQ + arow * 256 + SWZ64(arow, q) * 16);
            }
            {
                const uint32_t q = 4 * p + 2 + aqh;
                ldsm4(af1, smQ + arow * 256 + SWZ64(arow, q) * 16);
            }
            #pragma unroll
            for (int nt = 0; nt < 8; nt++) {
                const int row = nt * 8 + b8;
                const uint32_t q = 4 * p + bqh;
                uint32_t bf[4];
                ldsm4(bf, smK + row * 256 + SWZ64(row, q) * 16);
                mma8(s[nt], af0, bf[0], bf[1]);
                mma8(s[nt], af1, bf[2], bf[3]);
            }
        }

        // ---- online softmax (rows r0 = wid*16+r4, r1 = r0+8) ----
        float mx0 = -1e30f, mx1 = -1e30f;
        #pragma unroll
        for (int nt = 0; nt < 8; nt++) {
            mx0 = fmaxf(mx0, fmaxf(s[nt][0], s[nt][1]));
            mx1 = fmaxf(mx1, fmaxf(s[nt][2], s[nt][3]));
        }
        mx0 = fmaxf(mx0, __shfl_xor_sync(0xffffffffu, mx0, 1));
        mx0 = fmaxf(mx0, __shfl_xor_sync(0xffffffffu, mx0, 2));
        mx1 = fmaxf(mx1, __shfl_xor_sync(0xffffffffu, mx1, 1));
        mx1 = fmaxf(mx1, __shfl_xor_sync(0xffffffffu, mx1, 2));

        const float mn0 = fmaxf(m0r, mx0 * SC + cb);
        const float mn1 = fmaxf(m1r, mx1 * SC + cb);
        const float rs0 = __expf(m0r - mn0);
        const float rs1 = __expf(m1r - mn1);
        m0r = mn0; m1r = mn1;

        const int row0 = wid * 16 + r4;
        const int row1 = row0 + 8;
        float sum0 = 0.f, sum1 = 0.f;
        #pragma unroll
        for (int nt = 0; nt < 8; nt++) {
            uint32_t p00 = tf32r(__expf(s[nt][0] * SC + cb - mn0));
            uint32_t p01 = tf32r(__expf(s[nt][1] * SC + cb - mn0));
            uint32_t p10 = tf32r(__expf(s[nt][2] * SC + cb - mn1));
            uint32_t p11 = tf32r(__expf(s[nt][3] * SC + cb - mn1));
            sum0 += __uint_as_float(p00) + __uint_as_float(p01);
            sum1 += __uint_as_float(p10) + __uint_as_float(p11);
            const int qd = nt * 2 + (q2 >> 2);
            const int i0 = row0 * 64 + SWZ64(row0, qd) * 4 + (q2 & 3);
            const int i1 = row1 * 64 + SWZ64(row1, qd) * 4 + (q2 & 3);
            *(uint2*)&Ps[i0] = make_uint2(p00, p01);
            *(uint2*)&Ps[i1] = make_uint2(p10, p11);
        }
        sum0 += __shfl_xor_sync(0xffffffffu, sum0, 1);
        sum0 += __shfl_xor_sync(0xffffffffu, sum0, 2);
        sum1 += __shfl_xor_sync(0xffffffffu, sum1, 1);
        sum1 += __shfl_xor_sync(0xffffffffu, sum1, 2);
        l0 = l0 * rs0 + sum0;
        l1 = l1 * rs1 + sum1;

        #pragma unroll
        for (int nt = 0; nt < 8; nt++) {
            o[nt][0] *= rs0; o[nt][1] *= rs0;
            o[nt][2] *= rs1; o[nt][3] *= rs1;
        }
        __syncwarp();

        // ---- O += P V (per-warp 16x64, contraction over 64 keys) ----
        #pragma unroll
        for (int p = 0; p < 4; p++) {
            uint32_t af0[4], af1[4];
            {
                const uint32_t q = 4 * p + aqh;
                ldsm4(af0, smP + arow * 256 + SWZ64(arow, q) * 16);
            }
            {
                const uint32_t q = 4 * p + 2 + aqh;
                ldsm4(af1, smP + arow * 256 + SWZ64(arow, q) * 16);
            }
            #pragma unroll
            for (int nt = 0; nt < 8; nt++) {
                const int row = nt * 8 + b8;   // d index
                const uint32_t q = 4 * p + bqh;
                uint32_t bf[4];
                ldsm4(bf, smV + row * 256 + SWZ64(row, q) * 16);
                mma8(o[nt], af0, bf[0], bf[1]);
                mma8(o[nt], af1, bf[2], bf[3]);
            }
        }
    }

    // ---- normalize + write out (b, s, h*64+d) ----
    const float inv0 = 1.f / l0;
    const float inv1 = 1.f / l1;
    const int bb = bh >> 4, hh = bh & 15;
    const int gq0 = q0 + wid * 16 + r4;
    float* op0 = out + ((size_t)(bb * S_ + gq0)) * D_ + hh * DK;
    float* op1 = out + ((size_t)(bb * S_ + gq0 + 8)) * D_ + hh * DK;
    #pragma unroll
    for (int nt = 0; nt < 8; nt++) {
        const int d = nt * 8 + q2;
        float2 v0, v1;
        v0.x = o[nt][0] * inv0; v0.y = o[nt][1] * inv0;
        v1.x = o[nt][2] * inv1; v1.y = o[nt][3] * inv1;
        *(float2*)&op0[d] = v0;
        *(float2*)&op1[d] = v1;
    }
}

// ---------------------------------------------------------------------------
extern "C" void kernel_launch(void* const* d_in, const int* in_sizes, int n_in,
                              void* d_out, int out_size)
{
    const float* Xs  = (const float*)d_in[0];
    const float* Xt  = (const float*)d_in[1];
    const float* Wqs = (const float*)d_in[2];
    const float* bqs = (const float*)d_in[3];
    const float* Wqt = (const float*)d_in[4];
    const float* bqt = (const float*)d_in[5];
    const float* Wks = (const float*)d_in[6];
    const float* bks = (const float*)d_in[7];
    const float* Wkt = (const float*)d_in[8];
    const float* bkt = (const float*)d_in[9];
    const float* Wvs = (const float*)d_in[10];
    const float* bvs = (const float*)d_in[11];
    const float* Wvt = (const float*)d_in[12];
    const float* bvt = (const float*)d_in[13];
    const float* attn_bias = (const float*)d_in[14];
    float* out = (float*)d_out;

    cudaFuncSetAttribute(attn_mma, cudaFuncAttributeMaxDynamicSharedMemorySize,
                         98304);

    dim3 gGrid(64, 24);
    qkv_gemm_mma<<<gGrid, 256>>>(Xs, Xt, Wqs, bqs, Wqt, bqt,
                                 Wks, bks, Wkt, bkt, Wvs, bvs, Wvt, bvt);

    dim3 aGrid(16, B_ * H_);
    attn_mma<<<aGrid, 256, 98304>>>(attn_bias, out);
}